// round 3
// baseline (speedup 1.0000x reference)
#include <cuda_runtime.h>
#include <cuda_fp16.h>
#include <math.h>

#define D_HID   128
#define MAX_G   16384
#define MAX_N   65536
#define NT      128
#define SCAN_BS 128

// Scratch (allocation-free rule: __device__ globals)
__device__ __half g_H16[(size_t)MAX_N * D_HID];   // 16 MB fp16 copy of H
__device__ int    g_off[MAX_G + 1];

// ---------------------------------------------------------------------------
// Kernel A: convert H (f32) -> g_H16 (fp16). float4 in, 8B out per thread.
// ---------------------------------------------------------------------------
__global__ void convert_kernel(const float4* __restrict__ H4, int n4) {
    int i = blockIdx.x * blockDim.x + threadIdx.x;
    if (i < n4) {
        float4 v = H4[i];
        __half2 a = __floats2half2_rn(v.x, v.y);
        __half2 b = __floats2half2_rn(v.z, v.w);
        uint2 u;
        u.x = *reinterpret_cast<unsigned int*>(&a);
        u.y = *reinterpret_cast<unsigned int*>(&b);
        reinterpret_cast<uint2*>(g_H16)[i] = u;
    }
}

// ---------------------------------------------------------------------------
// Kernel B: one-kernel exclusive scan of port_len -> g_off.
// Block b sums its full prefix directly (coalesced, L2-resident), then scans
// its own 128-element chunk in smem.
// ---------------------------------------------------------------------------
__global__ void __launch_bounds__(SCAN_BS)
scan_kernel(const int* __restrict__ plen, int G) {
    const int blk = blockIdx.x, tid = threadIdx.x;

    int pre = 0;
    const int lim = blk * SCAN_BS;
    for (int i = tid; i < lim; i += SCAN_BS) pre += plen[i];

    __shared__ int red[SCAN_BS];
    red[tid] = pre;
    __syncthreads();
    for (int off = SCAN_BS / 2; off > 0; off >>= 1) {
        if (tid < off) red[tid] += red[tid + off];
        __syncthreads();
    }
    const int base = red[0];
    __syncthreads();

    const int idx = lim + tid;
    const int v = (idx < G) ? plen[idx] : 0;
    __shared__ int sc[SCAN_BS];
    sc[tid] = v;
    __syncthreads();
    for (int off = 1; off < SCAN_BS; off <<= 1) {
        int t = (tid >= off) ? sc[tid - off] : 0;
        __syncthreads();
        sc[tid] += t;
        __syncthreads();
    }
    if (idx < G)      g_off[idx] = base + sc[tid] - v;
    if (idx == G - 1) g_off[G]   = base + sc[tid];
}

// ---------------------------------------------------------------------------
// Kernel C: fused per-sample kernel. One block (4 warps) per sample.
// Warp-per-row fp16 gather: lane l loads 4 halfs (dims 4l..4l+3) as uint2,
// warp w handles lines start+w, start+w+4, ... (4-deep unrolled chains).
// Epilogue: cross-warp combine, LOO correction (f32 H anchor row), normalize.
// ---------------------------------------------------------------------------
__global__ void __launch_bounds__(NT)
fused_kernel(const float* __restrict__ H,
             const float* __restrict__ w,
             const int*   __restrict__ nodes,
             const int*   __restrict__ anchor_idx,
             const int*   __restrict__ pf_gid,
             float*       __restrict__ out,
             int B, int G) {
    const int b    = blockIdx.x;
    const int tid  = threadIdx.x;
    const int wid  = tid >> 5;
    const int lane = tid & 31;

    const int g = pf_gid[b];
    const bool valid = (g >= 0) && (g < G);
    const int gc = min(max(g, 0), G - 1);
    const int anchor = anchor_idx[b];
    const int start = g_off[gc];
    const int end   = g_off[gc + 1];

    float4 acc[4];
    #pragma unroll
    for (int m = 0; m < 4; m++) acc[m] = make_float4(0.f, 0.f, 0.f, 0.f);
    float wa = 0.f, ws = 0.f, swa = 0.f, sws = 0.f;

    for (int t0 = start + wid; t0 < end; t0 += 16) {
        #pragma unroll
        for (int m = 0; m < 4; m++) {
            const int t = t0 + 4 * m;
            if (t < end) {
                const int   nd = nodes[t];   // uniform in warp -> broadcast
                const float ww = w[t];
                const float wwa = fabsf(ww);
                ws += ww; wa += wwa;
                if (nd == anchor) { sws += ww; swa += wwa; }
                const uint2 u = reinterpret_cast<const uint2*>(
                                    g_H16 + (size_t)nd * D_HID)[lane];
                const float2 f0 = __half22float2(*reinterpret_cast<const __half2*>(&u.x));
                const float2 f1 = __half22float2(*reinterpret_cast<const __half2*>(&u.y));
                acc[m].x += wwa * f0.x;
                acc[m].y += wwa * f0.y;
                acc[m].z += wwa * f1.x;
                acc[m].w += wwa * f1.y;
            }
        }
    }
    float4 at;
    at.x = (acc[0].x + acc[1].x) + (acc[2].x + acc[3].x);
    at.y = (acc[0].y + acc[1].y) + (acc[2].y + acc[3].y);
    at.z = (acc[0].z + acc[1].z) + (acc[2].z + acc[3].z);
    at.w = (acc[0].w + acc[1].w) + (acc[2].w + acc[3].w);

    // Cross-warp combine of vector partials: smem[w][d]
    __shared__ float sv[4][D_HID];
    sv[wid][4 * lane + 0] = at.x;
    sv[wid][4 * lane + 1] = at.y;
    sv[wid][4 * lane + 2] = at.z;
    sv[wid][4 * lane + 3] = at.w;

    // Scalar sums: all lanes in a warp hold identical values; lane 0 publishes.
    __shared__ float ssc[4][4];
    if (lane == 0) {
        ssc[wid][0] = wa; ssc[wid][1] = ws; ssc[wid][2] = swa; ssc[wid][3] = sws;
    }
    __syncthreads();

    const float accf = ((sv[0][tid] + sv[1][tid]) + (sv[2][tid] + sv[3][tid]));
    wa  = (ssc[0][0] + ssc[1][0]) + (ssc[2][0] + ssc[3][0]);
    ws  = (ssc[0][1] + ssc[1][1]) + (ssc[2][1] + ssc[3][1]);
    swa = (ssc[0][2] + ssc[1][2]) + (ssc[2][2] + ssc[3][2]);
    sws = (ssc[0][3] + ssc[1][3]) + (ssc[2][3] + ssc[3][3]);

    const float ha    = H[(size_t)anchor * D_HID + tid];  // f32 anchor row
    const float denom = fmaxf(wa - swa, 1e-12f);

    float v = (accf - swa * ha) / denom;
    float s = (ws - sws) / denom;
    if (!valid) { v = 0.f; s = 0.f; }
    const float vs = s * v;

    // Norms of both vectors (block reduce)
    __shared__ float r0[NT], r1[NT];
    r0[tid] = v * v; r1[tid] = vs * vs;
    __syncthreads();
    for (int off = NT / 2; off > 0; off >>= 1) {
        if (tid < off) { r0[tid] += r0[tid + off]; r1[tid] += r1[tid + off]; }
        __syncthreads();
    }
    const float na = sqrtf(r0[0]);
    const float ns = sqrtf(r1[0]);

    out[(size_t)b * D_HID + tid] = v / fmaxf(na, 1e-6f);
    out[(size_t)(B + b) * D_HID + tid] = (ns > 0.f) ? vs / fmaxf(ns, 1e-6f) : vs;
}

// ---------------------------------------------------------------------------
extern "C" void kernel_launch(void* const* d_in, const int* in_sizes, int n_in,
                              void* d_out, int out_size) {
    const float* H      = (const float*)d_in[0];   // [N, 128]
    const float* w      = (const float*)d_in[1];   // [L]
    const int*   anchor = (const int*)  d_in[2];   // [B]
    const int*   pfgid  = (const int*)  d_in[3];   // [B]
    const int*   nodes  = (const int*)  d_in[4];   // [L]
    const int*   plen   = (const int*)  d_in[5];   // [G]
    float* out = (float*)d_out;                    // [2, B, 128]

    const int B = in_sizes[2];
    const int G = in_sizes[5];
    const int n4 = in_sizes[0] / 4;                // float4 count of H
    const int nblk_s = (G + SCAN_BS - 1) / SCAN_BS;

    convert_kernel<<<(n4 + 255) / 256, 256>>>((const float4*)H, n4);
    scan_kernel<<<nblk_s, SCAN_BS>>>(plen, G);
    fused_kernel<<<B, NT>>>(H, w, nodes, anchor, pfgid, out, B, G);
}

// round 4
// speedup vs baseline: 1.1040x; 1.1040x over previous
#include <cuda_runtime.h>
#include <cuda_fp16.h>
#include <math.h>

#define D_HID   128
#define MAX_G   16384
#define MAX_N   65536
#define NT      128
#define SCAN_BS 128

// Scratch (allocation-free rule: __device__ globals)
__device__ __half g_H16[(size_t)MAX_N * D_HID];   // 16 MB fp16 copy of H
__device__ int    g_off[MAX_G + 1];

// ---------------------------------------------------------------------------
// Kernel A: convert H (f32) -> g_H16 (fp16). float4 in, 8B out per thread.
// ---------------------------------------------------------------------------
__global__ void convert_kernel(const float4* __restrict__ H4, int n4) {
    int i = blockIdx.x * blockDim.x + threadIdx.x;
    if (i < n4) {
        float4 v = H4[i];
        __half2 a = __floats2half2_rn(v.x, v.y);
        __half2 b = __floats2half2_rn(v.z, v.w);
        uint2 u;
        u.x = *reinterpret_cast<unsigned int*>(&a);
        u.y = *reinterpret_cast<unsigned int*>(&b);
        reinterpret_cast<uint2*>(g_H16)[i] = u;
    }
}

// ---------------------------------------------------------------------------
// Kernel B: one-kernel exclusive scan of port_len -> g_off.
// ---------------------------------------------------------------------------
__global__ void __launch_bounds__(SCAN_BS)
scan_kernel(const int* __restrict__ plen, int G) {
    const int blk = blockIdx.x, tid = threadIdx.x;

    int pre = 0;
    const int lim = blk * SCAN_BS;
    for (int i = tid; i < lim; i += SCAN_BS) pre += plen[i];

    __shared__ int red[SCAN_BS];
    red[tid] = pre;
    __syncthreads();
    for (int off = SCAN_BS / 2; off > 0; off >>= 1) {
        if (tid < off) red[tid] += red[tid + off];
        __syncthreads();
    }
    const int base = red[0];
    __syncthreads();

    const int idx = lim + tid;
    const int v = (idx < G) ? plen[idx] : 0;
    __shared__ int sc[SCAN_BS];
    sc[tid] = v;
    __syncthreads();
    for (int off = 1; off < SCAN_BS; off <<= 1) {
        int t = (tid >= off) ? sc[tid - off] : 0;
        __syncthreads();
        sc[tid] += t;
        __syncthreads();
    }
    if (idx < G)      g_off[idx] = base + sc[tid] - v;
    if (idx == G - 1) g_off[G]   = base + sc[tid];
}

// ---------------------------------------------------------------------------
// Kernel C: fused per-sample kernel. One block (128 thr) per sample.
// Stage (nodes, |w|) per 128-line tile in smem (no address dependency),
// then gather fp16 rows: thread = (row-group r = tid>>6, half2-col c = tid&63).
// 8 independent half2 loads in flight per thread.
// ---------------------------------------------------------------------------
__global__ void __launch_bounds__(NT)
fused_kernel(const float* __restrict__ H,
             const float* __restrict__ w,
             const int*   __restrict__ nodes,
             const int*   __restrict__ anchor_idx,
             const int*   __restrict__ pf_gid,
             float*       __restrict__ out,
             int B, int G) {
    const int b   = blockIdx.x;
    const int tid = threadIdx.x;
    const int r   = tid >> 6;     // row-group 0/1
    const int c   = tid & 63;     // half2 column

    const int g = pf_gid[b];
    const bool valid = (g >= 0) && (g < G);
    const int gc = min(max(g, 0), G - 1);
    const int anchor = anchor_idx[b];
    const int start = g_off[gc];
    const int end   = g_off[gc + 1];

    __shared__ float sw[NT];
    __shared__ int   sn[NT];

    float ax0=0.f, ay0=0.f, ax1=0.f, ay1=0.f;
    float ax2=0.f, ay2=0.f, ax3=0.f, ay3=0.f;
    float wa = 0.f, ws = 0.f, swa = 0.f, sws = 0.f;

    for (int base = start; base < end; base += NT) {
        const int cnt = min(NT, end - base);
        if (tid < cnt) {
            const float ww = w[base + tid];
            const int   nd = nodes[base + tid];
            const float wwa = fabsf(ww);
            ws += ww; wa += wwa;
            if (nd == anchor) { sws += ww; swa += wwa; }
            sw[tid] = wwa;
            sn[tid] = nd;
        }
        __syncthreads();
        for (int j = 0; j < cnt; j += 16) {
            #pragma unroll
            for (int m = 0; m < 8; m++) {
                const int line = j + 2 * m + r;
                if (line < cnt) {
                    const float ww = sw[line];
                    const __half2 h = reinterpret_cast<const __half2*>(
                        g_H16 + (size_t)sn[line] * D_HID)[c];
                    const float2 f = __half22float2(h);
                    switch (m & 3) {
                        case 0: ax0 += ww * f.x; ay0 += ww * f.y; break;
                        case 1: ax1 += ww * f.x; ay1 += ww * f.y; break;
                        case 2: ax2 += ww * f.x; ay2 += ww * f.y; break;
                        default: ax3 += ww * f.x; ay3 += ww * f.y; break;
                    }
                }
            }
        }
        __syncthreads();
    }
    const float fx = (ax0 + ax1) + (ax2 + ax3);
    const float fy = (ay0 + ay1) + (ay2 + ay3);

    // Combine row-groups: sv[r][dim]
    __shared__ float sv[2][D_HID];
    sv[r][2 * c + 0] = fx;
    sv[r][2 * c + 1] = fy;

    // Scalar block reduce
    __shared__ float r0[NT], r1[NT], r2[NT], r3[NT];
    r0[tid] = wa; r1[tid] = ws; r2[tid] = swa; r3[tid] = sws;
    __syncthreads();
    for (int off = NT / 2; off > 0; off >>= 1) {
        if (tid < off) {
            r0[tid] += r0[tid + off];
            r1[tid] += r1[tid + off];
            r2[tid] += r2[tid + off];
            r3[tid] += r3[tid + off];
        }
        __syncthreads();
    }
    wa = r0[0]; ws = r1[0]; swa = r2[0]; sws = r3[0];
    const float accf = sv[0][tid] + sv[1][tid];
    __syncthreads();

    const float ha    = H[(size_t)anchor * D_HID + tid];  // f32 anchor row
    const float denom = fmaxf(wa - swa, 1e-12f);

    float v = (accf - swa * ha) / denom;
    float s = (ws - sws) / denom;
    if (!valid) { v = 0.f; s = 0.f; }
    const float vs = s * v;

    // Norms of both vectors
    r0[tid] = v * v; r1[tid] = vs * vs;
    __syncthreads();
    for (int off = NT / 2; off > 0; off >>= 1) {
        if (tid < off) { r0[tid] += r0[tid + off]; r1[tid] += r1[tid + off]; }
        __syncthreads();
    }
    const float na = sqrtf(r0[0]);
    const float ns = sqrtf(r1[0]);

    out[(size_t)b * D_HID + tid] = v / fmaxf(na, 1e-6f);
    out[(size_t)(B + b) * D_HID + tid] = (ns > 0.f) ? vs / fmaxf(ns, 1e-6f) : vs;
}

// ---------------------------------------------------------------------------
extern "C" void kernel_launch(void* const* d_in, const int* in_sizes, int n_in,
                              void* d_out, int out_size) {
    const float* H      = (const float*)d_in[0];   // [N, 128]
    const float* w      = (const float*)d_in[1];   // [L]
    const int*   anchor = (const int*)  d_in[2];   // [B]
    const int*   pfgid  = (const int*)  d_in[3];   // [B]
    const int*   nodes  = (const int*)  d_in[4];   // [L]
    const int*   plen   = (const int*)  d_in[5];   // [G]
    float* out = (float*)d_out;                    // [2, B, 128]

    const int B = in_sizes[2];
    const int G = in_sizes[5];
    const int n4 = in_sizes[0] / 4;
    const int nblk_s = (G + SCAN_BS - 1) / SCAN_BS;

    convert_kernel<<<(n4 + 255) / 256, 256>>>((const float4*)H, n4);
    scan_kernel<<<nblk_s, SCAN_BS>>>(plen, G);
    fused_kernel<<<B, NT>>>(H, w, nodes, anchor, pfgid, out, B, G);
}

// round 5
// speedup vs baseline: 1.4901x; 1.3498x over previous
#include <cuda_runtime.h>
#include <cuda_fp16.h>
#include <math.h>

#define D_HID   128
#define MAX_G   16384
#define MAX_N   65536
#define NT      128
#define SCAN_BS 128

// Scratch (allocation-free rule: __device__ globals)
__device__ __half g_H16[(size_t)MAX_N * D_HID];   // 16 MB fp16 copy of H
__device__ int    g_off[MAX_G + 1];

// ---------------------------------------------------------------------------
// Kernel A: convert H (f32) -> g_H16 (fp16). 4 independent float4 per thread.
// ---------------------------------------------------------------------------
__global__ void convert_kernel(const float4* __restrict__ H4, int n4) {
    const int base = blockIdx.x * 1024 + threadIdx.x;
    #pragma unroll
    for (int k = 0; k < 4; k++) {
        const int i = base + k * 256;
        if (i < n4) {
            float4 v = H4[i];
            __half2 a = __floats2half2_rn(v.x, v.y);
            __half2 b = __floats2half2_rn(v.z, v.w);
            uint2 u;
            u.x = *reinterpret_cast<unsigned int*>(&a);
            u.y = *reinterpret_cast<unsigned int*>(&b);
            reinterpret_cast<uint2*>(g_H16)[i] = u;
        }
    }
}

// ---------------------------------------------------------------------------
// Kernel B: one-kernel exclusive scan of port_len -> g_off.
// ---------------------------------------------------------------------------
__global__ void __launch_bounds__(SCAN_BS)
scan_kernel(const int* __restrict__ plen, int G) {
    const int blk = blockIdx.x, tid = threadIdx.x;

    int pre = 0;
    const int lim = blk * SCAN_BS;
    for (int i = tid; i < lim; i += SCAN_BS) pre += plen[i];

    __shared__ int red[SCAN_BS];
    red[tid] = pre;
    __syncthreads();
    for (int off = SCAN_BS / 2; off > 0; off >>= 1) {
        if (tid < off) red[tid] += red[tid + off];
        __syncthreads();
    }
    const int base = red[0];
    __syncthreads();

    const int idx = lim + tid;
    const int v = (idx < G) ? plen[idx] : 0;
    __shared__ int sc[SCAN_BS];
    sc[tid] = v;
    __syncthreads();
    for (int off = 1; off < SCAN_BS; off <<= 1) {
        int t = (tid >= off) ? sc[tid - off] : 0;
        __syncthreads();
        sc[tid] += t;
        __syncthreads();
    }
    if (idx < G)      g_off[idx] = base + sc[tid] - v;
    if (idx == G - 1) g_off[G]   = base + sc[tid];
}

// ---------------------------------------------------------------------------
// Kernel C: fused per-sample kernel. One block (128 thr) per sample.
// Stage (nodes, |w|) per 128-line tile in smem, then gather fp16 rows with
// LDG.128: thread = (line-slot s = tid>>4, 16B-chunk c = tid&15).
// Each thread accumulates 8 dims; slots combined through smem at the end.
// ---------------------------------------------------------------------------
__global__ void __launch_bounds__(NT)
fused_kernel(const float* __restrict__ H,
             const float* __restrict__ w,
             const int*   __restrict__ nodes,
             const int*   __restrict__ anchor_idx,
             const int*   __restrict__ pf_gid,
             float*       __restrict__ out,
             int B, int G) {
    const int b    = blockIdx.x;
    const int tid  = threadIdx.x;
    const int wid  = tid >> 5;
    const int lane = tid & 31;
    const int s    = tid >> 4;    // line slot 0..7
    const int c    = tid & 15;    // 16B chunk 0..15 (8 halfs)

    const int g = pf_gid[b];
    const bool valid = (g >= 0) && (g < G);
    const int gc = min(max(g, 0), G - 1);
    const int anchor = anchor_idx[b];
    const int start = g_off[gc];
    const int end   = g_off[gc + 1];

    __shared__ float sw[NT];
    __shared__ int   sn[NT];

    float acc[8];
    #pragma unroll
    for (int k = 0; k < 8; k++) acc[k] = 0.f;
    float wa = 0.f, ws = 0.f, swa = 0.f, sws = 0.f;

    for (int base = start; base < end; base += NT) {
        const int cnt = min(NT, end - base);
        if (tid < cnt) {
            const float ww = w[base + tid];
            const int   nd = nodes[base + tid];
            const float wwa = fabsf(ww);
            ws += ww; wa += wwa;
            if (nd == anchor) { sws += ww; swa += wwa; }
            sw[tid] = wwa;
            sn[tid] = nd;
        }
        __syncthreads();
        #pragma unroll 4
        for (int j = s; j < cnt; j += 8) {
            const float ww = sw[j];
            const uint4 u = *reinterpret_cast<const uint4*>(
                g_H16 + (size_t)sn[j] * D_HID + c * 8);
            const float2 f0 = __half22float2(*reinterpret_cast<const __half2*>(&u.x));
            const float2 f1 = __half22float2(*reinterpret_cast<const __half2*>(&u.y));
            const float2 f2 = __half22float2(*reinterpret_cast<const __half2*>(&u.z));
            const float2 f3 = __half22float2(*reinterpret_cast<const __half2*>(&u.w));
            acc[0] += ww * f0.x;  acc[1] += ww * f0.y;
            acc[2] += ww * f1.x;  acc[3] += ww * f1.y;
            acc[4] += ww * f2.x;  acc[5] += ww * f2.y;
            acc[6] += ww * f3.x;  acc[7] += ww * f3.y;
        }
        __syncthreads();
    }

    // ---- combine the 8 line-slots: sv[s][dim] ----
    __shared__ float sv[8][D_HID];
    #pragma unroll
    for (int k = 0; k < 8; k++) sv[s][c * 8 + k] = acc[k];

    // ---- scalar sums: warp shuffle reduce, then cross-warp ----
    #pragma unroll
    for (int o = 16; o > 0; o >>= 1) {
        wa  += __shfl_xor_sync(0xffffffff, wa,  o);
        ws  += __shfl_xor_sync(0xffffffff, ws,  o);
        swa += __shfl_xor_sync(0xffffffff, swa, o);
        sws += __shfl_xor_sync(0xffffffff, sws, o);
    }
    __shared__ float ssum[4][4];
    if (lane == 0) {
        ssum[wid][0] = wa; ssum[wid][1] = ws;
        ssum[wid][2] = swa; ssum[wid][3] = sws;
    }
    __syncthreads();
    wa  = (ssum[0][0] + ssum[1][0]) + (ssum[2][0] + ssum[3][0]);
    ws  = (ssum[0][1] + ssum[1][1]) + (ssum[2][1] + ssum[3][1]);
    swa = (ssum[0][2] + ssum[1][2]) + (ssum[2][2] + ssum[3][2]);
    sws = (ssum[0][3] + ssum[1][3]) + (ssum[2][3] + ssum[3][3]);

    float accf = 0.f;
    #pragma unroll
    for (int k = 0; k < 8; k++) accf += sv[k][tid];

    const float ha    = H[(size_t)anchor * D_HID + tid];   // f32 anchor row
    const float denom = fmaxf(wa - swa, 1e-12f);

    float v = (accf - swa * ha) / denom;
    float sc2 = (ws - sws) / denom;
    if (!valid) { v = 0.f; sc2 = 0.f; }
    const float vs = sc2 * v;

    // ---- norms: shuffle reduce + cross-warp ----
    float nv = v * v, nq = vs * vs;
    #pragma unroll
    for (int o = 16; o > 0; o >>= 1) {
        nv += __shfl_xor_sync(0xffffffff, nv, o);
        nq += __shfl_xor_sync(0xffffffff, nq, o);
    }
    __shared__ float snrm[4][2];
    if (lane == 0) { snrm[wid][0] = nv; snrm[wid][1] = nq; }
    __syncthreads();
    const float na = sqrtf((snrm[0][0] + snrm[1][0]) + (snrm[2][0] + snrm[3][0]));
    const float ns = sqrtf((snrm[0][1] + snrm[1][1]) + (snrm[2][1] + snrm[3][1]));

    out[(size_t)b * D_HID + tid] = v / fmaxf(na, 1e-6f);
    out[(size_t)(B + b) * D_HID + tid] = (ns > 0.f) ? vs / fmaxf(ns, 1e-6f) : vs;
}

// ---------------------------------------------------------------------------
extern "C" void kernel_launch(void* const* d_in, const int* in_sizes, int n_in,
                              void* d_out, int out_size) {
    const float* H      = (const float*)d_in[0];   // [N, 128]
    const float* w      = (const float*)d_in[1];   // [L]
    const int*   anchor = (const int*)  d_in[2];   // [B]
    const int*   pfgid  = (const int*)  d_in[3];   // [B]
    const int*   nodes  = (const int*)  d_in[4];   // [L]
    const int*   plen   = (const int*)  d_in[5];   // [G]
    float* out = (float*)d_out;                    // [2, B, 128]

    const int B = in_sizes[2];
    const int G = in_sizes[5];
    const int n4 = in_sizes[0] / 4;
    const int nblk_s = (G + SCAN_BS - 1) / SCAN_BS;
    const int nblk_c = (n4 + 1023) / 1024;

    convert_kernel<<<nblk_c, 256>>>((const float4*)H, n4);
    scan_kernel<<<nblk_s, SCAN_BS>>>(plen, G);
    fused_kernel<<<B, NT>>>(H, w, nodes, anchor, pfgid, out, B, G);
}

// round 6
// speedup vs baseline: 2.3070x; 1.5481x over previous
#include <cuda_runtime.h>
#include <cuda_fp16.h>
#include <math.h>

#define D_HID   128
#define MAX_G   16384
#define MAX_N   65536
#define SCAN_T  256

// Scratch (allocation-free rule: __device__ globals)
__device__ __half g_H16[(size_t)MAX_N * D_HID];   // 16 MB fp16 copy of H
__device__ int    g_off[MAX_G + 1];

// ---------------------------------------------------------------------------
// Kernel A (merged): blocks [0, nconv) convert H f32 -> fp16 with 16B stores;
// blocks [nconv, nconv+nscan) do the exclusive scan of port_len -> g_off.
// ---------------------------------------------------------------------------
__global__ void __launch_bounds__(SCAN_T)
prolog_kernel(const float4* __restrict__ H4, int n16,
              const int* __restrict__ plen, int G, int nconv) {
    const int tid = threadIdx.x;

    if (blockIdx.x < nconv) {
        // ---- convert: each thread 4 independent (2xfloat4 -> uint4) ops ----
        const int base = blockIdx.x * (SCAN_T * 4) + tid;
        #pragma unroll
        for (int k = 0; k < 4; k++) {
            const int i = base + k * SCAN_T;
            if (i < n16) {
                const float4 v0 = H4[2 * i];
                const float4 v1 = H4[2 * i + 1];
                __half2 a = __floats2half2_rn(v0.x, v0.y);
                __half2 b = __floats2half2_rn(v0.z, v0.w);
                __half2 cc = __floats2half2_rn(v1.x, v1.y);
                __half2 d = __floats2half2_rn(v1.z, v1.w);
                uint4 u;
                u.x = *reinterpret_cast<unsigned int*>(&a);
                u.y = *reinterpret_cast<unsigned int*>(&b);
                u.z = *reinterpret_cast<unsigned int*>(&cc);
                u.w = *reinterpret_cast<unsigned int*>(&d);
                reinterpret_cast<uint4*>(g_H16)[i] = u;
            }
        }
        return;
    }

    // ---- scan ----
    const int blk = blockIdx.x - nconv;
    int pre = 0;
    const int lim = blk * SCAN_T;
    for (int i = tid; i < lim; i += SCAN_T) pre += plen[i];

    __shared__ int red[SCAN_T];
    red[tid] = pre;
    __syncthreads();
    for (int off = SCAN_T / 2; off > 0; off >>= 1) {
        if (tid < off) red[tid] += red[tid + off];
        __syncthreads();
    }
    const int base = red[0];
    __syncthreads();

    const int idx = lim + tid;
    const int v = (idx < G) ? plen[idx] : 0;
    __shared__ int sc[SCAN_T];
    sc[tid] = v;
    __syncthreads();
    for (int off = 1; off < SCAN_T; off <<= 1) {
        int t = (tid >= off) ? sc[tid - off] : 0;
        __syncthreads();
        sc[tid] += t;
        __syncthreads();
    }
    if (idx < G)      g_off[idx] = base + sc[tid] - v;
    if (idx == G - 1) g_off[G]   = base + sc[tid];
}

// ---------------------------------------------------------------------------
// Kernel B: fused per-sample kernel — ONE WARP PER SAMPLE, no block syncs.
// lane = (slot s = lane>>4 in {0,1}, chunk c = lane&15).
// Tile of 64 lines: lanes stage (nodes,|w|) into a per-warp smem slice,
// then each lane gathers lines j = s, s+2, ... (32 LDG.128 per warp-tile).
// Slot combine via shfl_xor(16); scalars & norms via shuffles only.
// ---------------------------------------------------------------------------
__global__ void __launch_bounds__(256)
fused_kernel(const float* __restrict__ H,
             const float* __restrict__ w,
             const int*   __restrict__ nodes,
             const int*   __restrict__ anchor_idx,
             const int*   __restrict__ pf_gid,
             float*       __restrict__ out,
             int B, int G) {
    const int wslot = threadIdx.x >> 5;
    const int b     = blockIdx.x * 8 + wslot;
    if (b >= B) return;
    const int lane = threadIdx.x & 31;
    const int s    = lane >> 4;
    const int c    = lane & 15;

    const int g = pf_gid[b];
    const bool valid = (g >= 0) && (g < G);
    const int gc = min(max(g, 0), G - 1);
    const int anchor = anchor_idx[b];
    const int start = g_off[gc];
    const int end   = g_off[gc + 1];

    __shared__ float sw[8][64];
    __shared__ int   sn[8][64];

    float acc[8];
    #pragma unroll
    for (int k = 0; k < 8; k++) acc[k] = 0.f;
    float wa = 0.f, ws = 0.f, swa = 0.f, sws = 0.f;

    for (int base = start; base < end; base += 64) {
        const int cnt = min(64, end - base);
        // stage two lines per lane
        if (lane < cnt) {
            const float ww = w[base + lane];
            const int   nd = nodes[base + lane];
            const float wwa = fabsf(ww);
            ws += ww; wa += wwa;
            if (nd == anchor) { sws += ww; swa += wwa; }
            sw[wslot][lane] = wwa;
            sn[wslot][lane] = nd;
        }
        if (32 + lane < cnt) {
            const float ww = w[base + 32 + lane];
            const int   nd = nodes[base + 32 + lane];
            const float wwa = fabsf(ww);
            ws += ww; wa += wwa;
            if (nd == anchor) { sws += ww; swa += wwa; }
            sw[wslot][32 + lane] = wwa;
            sn[wslot][32 + lane] = nd;
        }
        __syncwarp();
        #pragma unroll 4
        for (int j = s; j < cnt; j += 2) {
            const float ww = sw[wslot][j];
            const uint4 u = *reinterpret_cast<const uint4*>(
                g_H16 + (size_t)sn[wslot][j] * D_HID + c * 8);
            const float2 f0 = __half22float2(*reinterpret_cast<const __half2*>(&u.x));
            const float2 f1 = __half22float2(*reinterpret_cast<const __half2*>(&u.y));
            const float2 f2 = __half22float2(*reinterpret_cast<const __half2*>(&u.z));
            const float2 f3 = __half22float2(*reinterpret_cast<const __half2*>(&u.w));
            acc[0] += ww * f0.x;  acc[1] += ww * f0.y;
            acc[2] += ww * f1.x;  acc[3] += ww * f1.y;
            acc[4] += ww * f2.x;  acc[5] += ww * f2.y;
            acc[6] += ww * f3.x;  acc[7] += ww * f3.y;
        }
        __syncwarp();
    }

    // ---- combine the 2 slots: after this every lane holds the full 8-dim sum
    #pragma unroll
    for (int k = 0; k < 8; k++)
        acc[k] += __shfl_xor_sync(0xffffffff, acc[k], 16);

    // ---- scalar sums: full-warp shuffle reduce ----
    #pragma unroll
    for (int o = 16; o > 0; o >>= 1) {
        wa  += __shfl_xor_sync(0xffffffff, wa,  o);
        ws  += __shfl_xor_sync(0xffffffff, ws,  o);
        swa += __shfl_xor_sync(0xffffffff, swa, o);
        sws += __shfl_xor_sync(0xffffffff, sws, o);
    }

    // ---- anchor row (f32), dims c*8 .. c*8+7 ----
    const float4* Ha4 = reinterpret_cast<const float4*>(H + (size_t)anchor * D_HID);
    const float4 h0 = Ha4[2 * c];
    const float4 h1 = Ha4[2 * c + 1];
    const float ha[8] = { h0.x, h0.y, h0.z, h0.w, h1.x, h1.y, h1.z, h1.w };

    const float denom = fmaxf(wa - swa, 1e-12f);
    const float inv_d = 1.f / denom;
    float sscale = (ws - sws) * inv_d;

    float v[8], vs[8];
    float nv = 0.f, nq = 0.f;
    #pragma unroll
    for (int k = 0; k < 8; k++) {
        float vk = (acc[k] - swa * ha[k]) * inv_d;
        if (!valid) vk = 0.f;
        v[k] = vk;
        const float vq = (valid ? sscale : 0.f) * vk;
        vs[k] = vq;
        nv += vk * vk;
        nq += vq * vq;
    }
    // norm reduce within 16-lane halves (halves hold identical data)
    #pragma unroll
    for (int o = 8; o > 0; o >>= 1) {
        nv += __shfl_xor_sync(0xffffffff, nv, o);
        nq += __shfl_xor_sync(0xffffffff, nq, o);
    }
    const float na = sqrtf(nv);
    const float ns = sqrtf(nq);

    // lanes 0-15 store V_abs, lanes 16-31 store V_sgn
    float o8[8];
    float* dst;
    if (s == 0) {
        const float inv = 1.f / fmaxf(na, 1e-6f);
        #pragma unroll
        for (int k = 0; k < 8; k++) o8[k] = v[k] * inv;
        dst = out + (size_t)b * D_HID + c * 8;
    } else {
        const float inv = (ns > 0.f) ? 1.f / fmaxf(ns, 1e-6f) : 1.f;
        #pragma unroll
        for (int k = 0; k < 8; k++) o8[k] = vs[k] * inv;
        dst = out + (size_t)(B + b) * D_HID + c * 8;
    }
    reinterpret_cast<float4*>(dst)[0] = make_float4(o8[0], o8[1], o8[2], o8[3]);
    reinterpret_cast<float4*>(dst)[1] = make_float4(o8[4], o8[5], o8[6], o8[7]);
}

// ---------------------------------------------------------------------------
extern "C" void kernel_launch(void* const* d_in, const int* in_sizes, int n_in,
                              void* d_out, int out_size) {
    const float* H      = (const float*)d_in[0];   // [N, 128]
    const float* w      = (const float*)d_in[1];   // [L]
    const int*   anchor = (const int*)  d_in[2];   // [B]
    const int*   pfgid  = (const int*)  d_in[3];   // [B]
    const int*   nodes  = (const int*)  d_in[4];   // [L]
    const int*   plen   = (const int*)  d_in[5];   // [G]
    float* out = (float*)d_out;                    // [2, B, 128]

    const int B = in_sizes[2];
    const int G = in_sizes[5];
    const int n16 = in_sizes[0] / 8;               // uint4 groups of fp16 out
    const int nconv = (n16 + SCAN_T * 4 - 1) / (SCAN_T * 4);
    const int nscan = (G + SCAN_T - 1) / SCAN_T;

    prolog_kernel<<<nconv + nscan, SCAN_T>>>((const float4*)H, n16, plen, G, nconv);
    fused_kernel<<<(B + 7) / 8, 256>>>(H, w, nodes, anchor, pfgid, out, B, G);
}